// round 7
// baseline (speedup 1.0000x reference)
#include <cuda_runtime.h>

#define B_      32
#define NOTES_  78
#define T_      128
#define IN_     80
#define H_      128
#define NSEQ1   (B_ * NOTES_)          // 2496
#define SPB     17                      // sequences per block
#define NBLK    147                     // 147*17 = 2499 >= 2496, 1 block/SM
#define KK2     52                      // float4 k-slices per gate row (208 scalars / 4)
#define KK2PAD  56                      // padded for unconditional ring prefetch

// ---------------- device scratch (no allocations allowed) ----------------
__device__ float4 g_wpk4[KK2PAD * 512];                    // packed weights [kk2][row]
__device__ float  g_xpj[(size_t)NSEQ1 * T_ * 8];           // fused note-LSTM input projection

// ---------------- helpers ----------------
__device__ __forceinline__ float2 upk2(unsigned long long v) {
    float lo, hi;
    asm("mov.b64 {%0,%1}, %2;" : "=f"(lo), "=f"(hi) : "l"(v));
    float2 f; f.x = lo; f.y = hi; return f;
}
__device__ __forceinline__ void fma2(unsigned long long& a, unsigned long long w, unsigned long long d) {
    asm("fma.rn.f32x2 %0, %1, %2, %0;" : "+l"(a) : "l"(w), "l"(d));
}
__device__ __forceinline__ float sigf(float x)     { return __fdividef(1.f, 1.f + __expf(-x)); }
__device__ __forceinline__ float tanhfast(float x) { return 2.f * sigf(2.f * x) - 1.f; }
__device__ __forceinline__ unsigned smem_u32(const void* p) {
    unsigned a;
    asm("{ .reg .u64 t; cvta.to.shared.u64 t, %1; cvt.u32.u64 %0, t; }" : "=r"(a) : "l"(p));
    return a;
}

// ---------------- weight packing: [kk2][512] float4, k-major quads ----------------
__global__ void pack_w_kernel(const float* __restrict__ Wih, const float* __restrict__ Whh) {
    int idx = blockIdx.x * blockDim.x + threadIdx.x;
    if (idx >= KK2PAD * 512) return;
    int kk2 = idx >> 9;
    int r   = idx & 511;
    int k0  = 4 * kk2;
    float v[4];
    #pragma unroll
    for (int l = 0; l < 4; l++) {
        int k = k0 + l;
        float val = 0.f;
        if (k < IN_)                 val = Wih[r * IN_ + k];
        else if (k < IN_ + H_)       val = Whh[r * H_ + (k - IN_)];
        v[l] = val;
    }
    g_wpk4[kk2 * 512 + r] = make_float4(v[0], v[1], v[2], v[3]);
}

__global__ void sink_kernel() {}

// ---------------- stage 1: time LSTM, persistent, 512 thr = 1 row/thread ----------------
// row r = tid; gate = tid>>7 (0=i,1=f,2=g,3=o); j = tid&127.
// SMEM (dynamic): sdata[17][208] floats (x[0:80) | h[80:208)), act[4][128][17], sWn[8*128]
__global__ __launch_bounds__(512, 1) void stage1_kernel(
    const float* __restrict__ x,
    const float* __restrict__ bih, const float* __restrict__ bhh,
    const float* __restrict__ Wihn)
{
    extern __shared__ float smem[];
    float*  df   = smem;                        // 17*208 = 3536 floats
    float*  sact = smem + SPB * 208;            // 4*128*17 = 8704 floats
    float*  sWn  = sact + 4 * 128 * SPB;        // 1024 floats

    const int tid  = threadIdx.x;
    const int seq0 = blockIdx.x * SPB;
    const int gate = tid >> 7;
    const int j    = tid & 127;
    const float bias = bih[tid] + bhh[tid];

    for (int i = tid; i < 8 * H_; i += 512) sWn[i] = Wihn[i];
    for (int i = tid; i < SPB * 208; i += 512) df[i] = 0.f;   // zero h region (x overwritten)

    float c[SPB];
    #pragma unroll
    for (int s = 0; s < SPB; s++) c[s] = 0.f;

    const unsigned sb = smem_u32(df);
    const char* gw = reinterpret_cast<const char*>(g_wpk4);

    // x prefetch registers: threads 0..339 each hold one float4 of x(t)
    const int xs = tid / 20, xq = tid - xs * 20;   // valid when tid < 340
    float4 xr = make_float4(0, 0, 0, 0);
    float4* df4 = reinterpret_cast<float4*>(df);
    const float4* xg4 = reinterpret_cast<const float4*>(x);
    if (tid < SPB * 20) {
        int seq = seq0 + xs; if (seq >= NSEQ1) seq = NSEQ1 - 1;
        xr = xg4[((size_t)seq * T_ + 0) * 20 + xq];
    }

    for (int t = 0; t < T_; t++) {
        // ---- stage x(t) from registers into SMEM ----
        if (tid < SPB * 20) df4[xs * 52 + xq] = xr;
        __syncthreads();                       // x(t) & h(t-1) ready

        // ---- issue x(t+1) prefetch (latency hidden under matvec) ----
        if (tid < SPB * 20) {
            int tn = (t + 1 < T_) ? t + 1 : t;
            int seq = seq0 + xs; if (seq >= NSEQ1) seq = NSEQ1 - 1;
            xr = xg4[((size_t)seq * T_ + tn) * 20 + xq];
        }

        // ---- matvec: gate row tid over [x;h] for 17 seqs, f32x2 + 128-bit loads ----
        unsigned long long acc[SPB];
        #pragma unroll
        for (int s = 0; s < SPB; s++) acc[s] = 0ull;

        unsigned long long wr[4][2];           // ring: 4 float4 in flight
        #pragma unroll
        for (int p = 0; p < 4; p++)
            asm("ld.global.nc.v2.b64 {%0,%1}, [%2];"
                : "=l"(wr[p][0]), "=l"(wr[p][1])
                : "l"(gw + ((size_t)p * 512 + tid) * 16));

        #pragma unroll 4
        for (int i2 = 0; i2 < KK2; i2++) {
            const unsigned long long cw0 = wr[i2 & 3][0], cw1 = wr[i2 & 3][1];
            asm("ld.global.nc.v2.b64 {%0,%1}, [%2];"
                : "=l"(wr[i2 & 3][0]), "=l"(wr[i2 & 3][1])
                : "l"(gw + ((size_t)(i2 + 4) * 512 + tid) * 16));
            #pragma unroll
            for (int s = 0; s < SPB; s++) {
                unsigned long long d01, d23;
                asm("ld.shared.v2.b64 {%0,%1}, [%2];"
                    : "=l"(d01), "=l"(d23)
                    : "r"(sb + (unsigned)(s * 832 + i2 * 16)));
                fma2(acc[s], cw0, d01);
                fma2(acc[s], cw1, d23);
            }
        }

        // ---- activations (all 512 threads) -> act exchange ----
        #pragma unroll
        for (int s = 0; s < SPB; s++) {
            float2 a = upk2(acc[s]);
            float g = a.x + a.y + bias;
            float av = (gate == 2) ? tanhfast(g) : sigf(g);
            sact[gate * (128 * SPB) + j * SPB + s] = av;
        }
        __syncthreads();                       // act ready; matvec reads done

        // ---- cell update + h(t) write (threads 0..127 own cell j) ----
        if (tid < 128) {
            #pragma unroll
            for (int s = 0; s < SPB; s++) {
                float ai = sact[0 * (128 * SPB) + j * SPB + s];
                float af = sact[1 * (128 * SPB) + j * SPB + s];
                float ag = sact[2 * (128 * SPB) + j * SPB + s];
                float ao = sact[3 * (128 * SPB) + j * SPB + s];
                c[s] = af * c[s] + ai * ag;
                df[s * 208 + 80 + j] = ao * tanhfast(c[s]);
            }
        }
        __syncthreads();                       // h(t) ready

        // ---- fused note-LSTM input projection (136 threads; others run ahead) ----
        if (tid < SPB * 8) {
            int s = tid >> 3, row = tid & 7;
            const float2* hv = reinterpret_cast<const float2*>(&df[s * 208 + 80]);
            const float2* wv = reinterpret_cast<const float2*>(&sWn[row * H_]);
            float a = 0.f;
            #pragma unroll
            for (int jj = 0; jj < 64; jj++) {
                float2 h2 = hv[jj], w2 = wv[jj];
                a = fmaf(h2.x, w2.x, fmaf(h2.y, w2.y, a));
            }
            int seq = seq0 + s;
            if (seq < NSEQ1) g_xpj[((size_t)seq * T_ + t) * 8 + row] = a;
        }
        // next iteration's x-store region is disjoint from h; its sync orders the rest
    }
}

// ---------------- stage 2: note LSTM (hidden=2), one thread per (b,t) ----------------
__global__ __launch_bounds__(128) void stage2_kernel(
    const float* __restrict__ Whhn,
    const float* __restrict__ bihn, const float* __restrict__ bhhn,
    float* __restrict__ out)
{
    int g = blockIdx.x * 128 + threadIdx.x;    // 0..4095
    int b = g >> 7, t = g & 127;

    float W[16];
    #pragma unroll
    for (int i = 0; i < 16; i++) W[i] = Whhn[i];
    float bs[8];
    #pragma unroll
    for (int i = 0; i < 8; i++) bs[i] = bihn[i] + bhhn[i];

    float h0 = 0.f, h1 = 0.f, c0 = 0.f, c1 = 0.f;
    const float4* xp = reinterpret_cast<const float4*>(g_xpj);
    float* op = out + ((size_t)b * T_ + t) * (NOTES_ * 2);

    for (int note = 0; note < NOTES_; note++) {
        size_t base = ((size_t)(b * NOTES_ + note) * T_ + t) * 2;
        float4 xa = xp[base];       // rows 0..3 : i0 i1 f0 f1
        float4 xb = xp[base + 1];   // rows 4..7 : g0 g1 o0 o1
        float gi0 = xa.x + bs[0] + W[0]  * h0 + W[1]  * h1;
        float gi1 = xa.y + bs[1] + W[2]  * h0 + W[3]  * h1;
        float gf0 = xa.z + bs[2] + W[4]  * h0 + W[5]  * h1;
        float gf1 = xa.w + bs[3] + W[6]  * h0 + W[7]  * h1;
        float gg0 = xb.x + bs[4] + W[8]  * h0 + W[9]  * h1;
        float gg1 = xb.y + bs[5] + W[10] * h0 + W[11] * h1;
        float go0 = xb.z + bs[6] + W[12] * h0 + W[13] * h1;
        float go1 = xb.w + bs[7] + W[14] * h0 + W[15] * h1;
        c0 = sigf(gf0) * c0 + sigf(gi0) * tanhfast(gg0);
        c1 = sigf(gf1) * c1 + sigf(gi1) * tanhfast(gg1);
        h0 = sigf(go0) * tanhfast(c0);
        h1 = sigf(go1) * tanhfast(c1);
        op[note * 2]     = h0;
        op[note * 2 + 1] = h1;
    }
}

// ---------------- launch ----------------
extern "C" void kernel_launch(void* const* d_in, const int* in_sizes, int n_in,
                              void* d_out, int out_size)
{
    const float* x     = (const float*)d_in[0];
    const float* Wih_t = (const float*)d_in[1];
    const float* Whh_t = (const float*)d_in[2];
    const float* bih_t = (const float*)d_in[3];
    const float* bhh_t = (const float*)d_in[4];
    const float* Wih_n = (const float*)d_in[5];
    const float* Whh_n = (const float*)d_in[6];
    const float* bih_n = (const float*)d_in[7];
    const float* bhh_n = (const float*)d_in[8];
    float* out = (float*)d_out;

    const int smem_bytes = (SPB * 208 + 4 * 128 * SPB + 8 * H_) * sizeof(float); // 53056
    cudaFuncSetAttribute(stage1_kernel, cudaFuncAttributeMaxDynamicSharedMemorySize, smem_bytes);

    // 4 launches/call so ncu (-s 5 -c 1) lands on stage1 (global launch #6)
    pack_w_kernel<<<(KK2PAD * 512 + 255) / 256, 256>>>(Wih_t, Whh_t);
    stage1_kernel<<<NBLK, 512, smem_bytes>>>(x, bih_t, bhh_t, Wih_n);
    stage2_kernel<<<(B_ * T_) / 128, 128>>>(Whh_n, bih_n, bhh_n, out);
    sink_kernel<<<1, 32>>>();
}

// round 8
// speedup vs baseline: 1.0600x; 1.0600x over previous
#include <cuda_runtime.h>

#define B_      32
#define NOTES_  78
#define T_      128
#define IN_     80
#define H_      128
#define NSEQ1   (B_ * NOTES_)          // 2496
#define SPB     17                      // sequences per block
#define NBLK    147                     // 147*17 = 2499 >= 2496, 1 block/SM
#define KK2     52                      // float4 k-slices per gate row (208 scalars / 4)
#define KK2PAD  56                      // padded for unconditional ring prefetch

// ---------------- device scratch (no allocations allowed) ----------------
__device__ float4 g_wpk4[KK2PAD * 512];                    // packed weights [kk2][row]
__device__ float  g_xpj[(size_t)NSEQ1 * T_ * 8];           // fused note-LSTM input projection

// ---------------- helpers ----------------
__device__ __forceinline__ float2 upk2(unsigned long long v) {
    float lo, hi;
    asm("mov.b64 {%0,%1}, %2;" : "=f"(lo), "=f"(hi) : "l"(v));
    float2 f; f.x = lo; f.y = hi; return f;
}
__device__ __forceinline__ void fma2(unsigned long long& a, unsigned long long w, unsigned long long d) {
    asm("fma.rn.f32x2 %0, %1, %2, %0;" : "+l"(a) : "l"(w), "l"(d));
}
__device__ __forceinline__ float sigf(float x)     { return __fdividef(1.f, 1.f + __expf(-x)); }
__device__ __forceinline__ float tanhfast(float x) { return 2.f * sigf(2.f * x) - 1.f; }
__device__ __forceinline__ unsigned smem_u32(const void* p) {
    unsigned a;
    asm("{ .reg .u64 t; cvta.to.shared.u64 t, %1; cvt.u32.u64 %0, t; }" : "=r"(a) : "l"(p));
    return a;
}

// ---------------- weight packing: [kk2][512] float4, k-major quads ----------------
__global__ void pack_w_kernel(const float* __restrict__ Wih, const float* __restrict__ Whh) {
    int idx = blockIdx.x * blockDim.x + threadIdx.x;
    if (idx >= KK2PAD * 512) return;
    int kk2 = idx >> 9;
    int r   = idx & 511;
    int k0  = 4 * kk2;
    float v[4];
    #pragma unroll
    for (int l = 0; l < 4; l++) {
        int k = k0 + l;
        float val = 0.f;
        if (k < IN_)                 val = Wih[r * IN_ + k];
        else if (k < IN_ + H_)       val = Whh[r * H_ + (k - IN_)];
        v[l] = val;
    }
    g_wpk4[kk2 * 512 + r] = make_float4(v[0], v[1], v[2], v[3]);
}

__global__ void sink_kernel() {}

// ---------------- stage 1: time LSTM, persistent, 512 thr = 1 row/thread ----------------
// row r = tid; gate = tid>>7 (0=i,1=f,2=g,3=o); j = tid&127.
// SMEM (dynamic): sdata[17][208] floats (x[0:80) | h[80:208)), act[4][128][17], sWn[8*128]
__global__ __launch_bounds__(512, 1) void stage1_kernel(
    const float* __restrict__ x,
    const float* __restrict__ bih, const float* __restrict__ bhh,
    const float* __restrict__ Wihn)
{
    extern __shared__ float smem[];
    float*  df   = smem;                        // 17*208 = 3536 floats
    float*  sact = smem + SPB * 208;            // 4*128*17 = 8704 floats
    float*  sWn  = sact + 4 * 128 * SPB;        // 1024 floats

    const int tid  = threadIdx.x;
    const int seq0 = blockIdx.x * SPB;
    const int gate = tid >> 7;
    const int j    = tid & 127;
    const float bias = bih[tid] + bhh[tid];

    for (int i = tid; i < 8 * H_; i += 512) sWn[i] = Wihn[i];
    for (int i = tid; i < SPB * 208; i += 512) df[i] = 0.f;   // zero h region (x overwritten)

    float c[SPB];
    #pragma unroll
    for (int s = 0; s < SPB; s++) c[s] = 0.f;

    const unsigned sb = smem_u32(df);
    const char* gw = reinterpret_cast<const char*>(g_wpk4);

    // x prefetch registers: threads 0..339 each hold one float4 of x(t)
    const int xs = tid / 20, xq = tid - xs * 20;   // valid when tid < 340
    float4 xr = make_float4(0, 0, 0, 0);
    float4* df4 = reinterpret_cast<float4*>(df);
    const float4* xg4 = reinterpret_cast<const float4*>(x);
    if (tid < SPB * 20) {
        int seq = seq0 + xs; if (seq >= NSEQ1) seq = NSEQ1 - 1;
        xr = xg4[((size_t)seq * T_ + 0) * 20 + xq];
    }

    for (int t = 0; t < T_; t++) {
        // ---- stage x(t) from registers into SMEM ----
        if (tid < SPB * 20) df4[xs * 52 + xq] = xr;
        __syncthreads();                       // x(t) & h(t-1) ready

        // ---- issue x(t+1) prefetch (latency hidden under matvec) ----
        if (tid < SPB * 20) {
            int tn = (t + 1 < T_) ? t + 1 : t;
            int seq = seq0 + xs; if (seq >= NSEQ1) seq = NSEQ1 - 1;
            xr = xg4[((size_t)seq * T_ + tn) * 20 + xq];
        }

        // ---- matvec: gate row tid over [x;h] for 17 seqs, f32x2 + 128-bit loads ----
        unsigned long long acc[SPB];
        #pragma unroll
        for (int s = 0; s < SPB; s++) acc[s] = 0ull;

        unsigned long long wr[4][2];           // ring: 4 float4 in flight
        #pragma unroll
        for (int p = 0; p < 4; p++)
            asm("ld.global.nc.v2.b64 {%0,%1}, [%2];"
                : "=l"(wr[p][0]), "=l"(wr[p][1])
                : "l"(gw + ((size_t)p * 512 + tid) * 16));

        #pragma unroll 4
        for (int i2 = 0; i2 < KK2; i2++) {
            const unsigned long long cw0 = wr[i2 & 3][0], cw1 = wr[i2 & 3][1];
            asm("ld.global.nc.v2.b64 {%0,%1}, [%2];"
                : "=l"(wr[i2 & 3][0]), "=l"(wr[i2 & 3][1])
                : "l"(gw + ((size_t)(i2 + 4) * 512 + tid) * 16));
            #pragma unroll
            for (int s = 0; s < SPB; s++) {
                unsigned long long d01, d23;
                asm("ld.shared.v2.b64 {%0,%1}, [%2];"
                    : "=l"(d01), "=l"(d23)
                    : "r"(sb + (unsigned)(s * 832 + i2 * 16)));
                fma2(acc[s], cw0, d01);
                fma2(acc[s], cw1, d23);
            }
        }

        // ---- activations (all 512 threads) -> act exchange ----
        #pragma unroll
        for (int s = 0; s < SPB; s++) {
            float2 a = upk2(acc[s]);
            float g = a.x + a.y + bias;
            float av = (gate == 2) ? tanhfast(g) : sigf(g);
            sact[gate * (128 * SPB) + j * SPB + s] = av;
        }
        __syncthreads();                       // act ready; matvec reads done

        // ---- cell update + h(t) write (threads 0..127 own cell j) ----
        if (tid < 128) {
            #pragma unroll
            for (int s = 0; s < SPB; s++) {
                float ai = sact[0 * (128 * SPB) + j * SPB + s];
                float af = sact[1 * (128 * SPB) + j * SPB + s];
                float ag = sact[2 * (128 * SPB) + j * SPB + s];
                float ao = sact[3 * (128 * SPB) + j * SPB + s];
                c[s] = af * c[s] + ai * ag;
                df[s * 208 + 80 + j] = ao * tanhfast(c[s]);
            }
        }
        __syncthreads();                       // h(t) ready

        // ---- fused note-LSTM input projection (136 threads; others run ahead) ----
        if (tid < SPB * 8) {
            int s = tid >> 3, row = tid & 7;
            const float2* hv = reinterpret_cast<const float2*>(&df[s * 208 + 80]);
            const float2* wv = reinterpret_cast<const float2*>(&sWn[row * H_]);
            float a = 0.f;
            #pragma unroll
            for (int jj = 0; jj < 64; jj++) {
                float2 h2 = hv[jj], w2 = wv[jj];
                a = fmaf(h2.x, w2.x, fmaf(h2.y, w2.y, a));
            }
            int seq = seq0 + s;
            if (seq < NSEQ1) g_xpj[((size_t)seq * T_ + t) * 8 + row] = a;
        }
        // next iteration's x-store region is disjoint from h; its sync orders the rest
    }
}

// ---------------- stage 2: note LSTM (hidden=2), one thread per (b,t) ----------------
__global__ __launch_bounds__(128) void stage2_kernel(
    const float* __restrict__ Whhn,
    const float* __restrict__ bihn, const float* __restrict__ bhhn,
    float* __restrict__ out)
{
    int g = blockIdx.x * 128 + threadIdx.x;    // 0..4095
    int b = g >> 7, t = g & 127;

    float W[16];
    #pragma unroll
    for (int i = 0; i < 16; i++) W[i] = Whhn[i];
    float bs[8];
    #pragma unroll
    for (int i = 0; i < 8; i++) bs[i] = bihn[i] + bhhn[i];

    float h0 = 0.f, h1 = 0.f, c0 = 0.f, c1 = 0.f;
    const float4* xp = reinterpret_cast<const float4*>(g_xpj);
    float* op = out + ((size_t)b * T_ + t) * (NOTES_ * 2);

    for (int note = 0; note < NOTES_; note++) {
        size_t base = ((size_t)(b * NOTES_ + note) * T_ + t) * 2;
        float4 xa = xp[base];       // rows 0..3 : i0 i1 f0 f1
        float4 xb = xp[base + 1];   // rows 4..7 : g0 g1 o0 o1
        float gi0 = xa.x + bs[0] + W[0]  * h0 + W[1]  * h1;
        float gi1 = xa.y + bs[1] + W[2]  * h0 + W[3]  * h1;
        float gf0 = xa.z + bs[2] + W[4]  * h0 + W[5]  * h1;
        float gf1 = xa.w + bs[3] + W[6]  * h0 + W[7]  * h1;
        float gg0 = xb.x + bs[4] + W[8]  * h0 + W[9]  * h1;
        float gg1 = xb.y + bs[5] + W[10] * h0 + W[11] * h1;
        float go0 = xb.z + bs[6] + W[12] * h0 + W[13] * h1;
        float go1 = xb.w + bs[7] + W[14] * h0 + W[15] * h1;
        c0 = sigf(gf0) * c0 + sigf(gi0) * tanhfast(gg0);
        c1 = sigf(gf1) * c1 + sigf(gi1) * tanhfast(gg1);
        h0 = sigf(go0) * tanhfast(c0);
        h1 = sigf(go1) * tanhfast(c1);
        op[note * 2]     = h0;
        op[note * 2 + 1] = h1;
    }
}

// ---------------- launch ----------------
extern "C" void kernel_launch(void* const* d_in, const int* in_sizes, int n_in,
                              void* d_out, int out_size)
{
    const float* x     = (const float*)d_in[0];
    const float* Wih_t = (const float*)d_in[1];
    const float* Whh_t = (const float*)d_in[2];
    const float* bih_t = (const float*)d_in[3];
    const float* bhh_t = (const float*)d_in[4];
    const float* Wih_n = (const float*)d_in[5];
    const float* Whh_n = (const float*)d_in[6];
    const float* bih_n = (const float*)d_in[7];
    const float* bhh_n = (const float*)d_in[8];
    float* out = (float*)d_out;

    const int smem_bytes = (SPB * 208 + 4 * 128 * SPB + 8 * H_) * sizeof(float); // 53056
    cudaFuncSetAttribute(stage1_kernel, cudaFuncAttributeMaxDynamicSharedMemorySize, smem_bytes);

    // 4 launches/call so ncu (-s 5 -c 1) lands on stage1 (global launch #6)
    pack_w_kernel<<<(KK2PAD * 512 + 255) / 256, 256>>>(Wih_t, Whh_t);
    stage1_kernel<<<NBLK, 512, smem_bytes>>>(x, bih_t, bhh_t, Wih_n);
    stage2_kernel<<<(B_ * T_) / 128, 128>>>(Whh_n, bih_n, bhh_n, out);
    sink_kernel<<<1, 32>>>();
}